// round 2
// baseline (speedup 1.0000x reference)
#include <cuda_runtime.h>
#include <cstdint>
#include <cstddef>

typedef unsigned long long ull;

#define Tlen 512
#define NB   4096
#define NTHR 800   // 25 warps; warp u owns hidden unit u

// ---- shared memory layout (float offsets), all 16B-aligned ----
#define W0_OFF    0                    // 100 rows x 28  = 2800  : L1 fused [Wih1|Whh1|pad2]
#define W123_OFF  2800                 // 3 x 100 x 52   = 15600 : L2-4 fused [Wih|0|Whh|0]
#define BIAS_OFF  (W123_OFF + 15600)   // 18400 : 4 x 100 fused (bih+bhh)
#define WFC_OFF   (BIAS_OFF + 400)     // 18800 : 52-float fc row (W_fc at [26..50])
#define V0_OFF    (WFC_OFF + 52)       // 18852 : [2 buf][32 lane][28]  L1 v-rows
#define V123_OFF  (V0_OFF + 1792)      // 20644 : [3 layer][2 buf][32][52]
#define SMEM_FLOATS (V123_OFF + 9984)  // 30628 floats = 122512 bytes

__device__ __forceinline__ ull pack2(float lo, float hi) {
    return (ull)__float_as_uint(lo) | ((ull)__float_as_uint(hi) << 32);
}
__device__ __forceinline__ void unpack2(ull v, float& lo, float& hi) {
    lo = __uint_as_float((unsigned)v);
    hi = __uint_as_float((unsigned)(v >> 32));
}
__device__ __forceinline__ void fma2(ull& acc, ull a, ull b) {
    asm("fma.rn.f32x2 %0, %1, %2, %0;" : "+l"(acc) : "l"(a), "l"(b));
}
__device__ __forceinline__ float fast_sig(float x) {
    float e, r;
    asm("ex2.approx.ftz.f32 %0, %1;" : "=f"(e) : "f"(x * -1.4426950408889634f));
    asm("rcp.approx.ftz.f32 %0, %1;" : "=f"(r) : "f"(e + 1.0f));
    return r;
}
__device__ __forceinline__ float fast_tanh(float x) {
    return fmaf(2.0f, fast_sig(2.0f * x), -1.0f);
}

// 4 gate dot-products sharing one v-row sweep. NCH = row length / 4.
template<int NCH>
__device__ __forceinline__ void gates4(const float* vrow,
    const float* w0, const float* w1, const float* w2, const float* w3,
    float b0, float b1, float b2, float b3,
    float& s0, float& s1, float& s2, float& s3)
{
    ull a0 = pack2(b0, 0.f), a1 = pack2(b1, 0.f), a2 = pack2(b2, 0.f), a3 = pack2(b3, 0.f);
    const ulonglong2* V  = (const ulonglong2*)vrow;
    const ulonglong2* W0 = (const ulonglong2*)w0;
    const ulonglong2* W1 = (const ulonglong2*)w1;
    const ulonglong2* W2 = (const ulonglong2*)w2;
    const ulonglong2* W3 = (const ulonglong2*)w3;
#pragma unroll
    for (int ch = 0; ch < NCH; ++ch) {
        ulonglong2 hv = V[ch];
        ulonglong2 w;
        w = W0[ch]; fma2(a0, w.x, hv.x); fma2(a0, w.y, hv.y);
        w = W1[ch]; fma2(a1, w.x, hv.x); fma2(a1, w.y, hv.y);
        w = W2[ch]; fma2(a2, w.x, hv.x); fma2(a2, w.y, hv.y);
        w = W3[ch]; fma2(a3, w.x, hv.x); fma2(a3, w.y, hv.y);
    }
    float lo, hi;
    unpack2(a0, lo, hi); s0 = lo + hi;
    unpack2(a1, lo, hi); s1 = lo + hi;
    unpack2(a2, lo, hi); s2 = lo + hi;
    unpack2(a3, lo, hi); s3 = lo + hi;
}

__device__ __forceinline__ float lstm_update(float s0, float s1, float s2, float s3, float& c) {
    float i = fast_sig(s0);
    float f = fast_sig(s1);
    float g = fast_tanh(s2);
    float o = fast_sig(s3);
    c = fmaf(f, c, i * g);
    return o * fast_tanh(c);
}

__device__ __forceinline__ float fc_dot(const float* vrow, const float* wrow) {
    ull a = 0ull;
    const ulonglong2* V = (const ulonglong2*)vrow;
    const ulonglong2* W = (const ulonglong2*)wrow;
#pragma unroll
    for (int ch = 0; ch < 13; ++ch) {
        ulonglong2 hv = V[ch];
        ulonglong2 w  = W[ch];
        fma2(a, w.x, hv.x); fma2(a, w.y, hv.y);
    }
    float lo, hi; unpack2(a, lo, hi);
    return lo + hi;
}

__global__ void __launch_bounds__(NTHR, 1) lstm_kernel(
    const float* __restrict__ x,
    const float* __restrict__ Wih1, const float* __restrict__ Whh1,
    const float* __restrict__ bih1, const float* __restrict__ bhh1,
    const float* __restrict__ Wih2, const float* __restrict__ Whh2,
    const float* __restrict__ bih2, const float* __restrict__ bhh2,
    const float* __restrict__ Wih3, const float* __restrict__ Whh3,
    const float* __restrict__ bih3, const float* __restrict__ bhh3,
    const float* __restrict__ Wih4, const float* __restrict__ Whh4,
    const float* __restrict__ bih4, const float* __restrict__ bhh4,
    const float* __restrict__ Wfc, const float* __restrict__ bfc,
    float* __restrict__ out, int write_states)
{
    extern __shared__ float smem[];
    const int tid = threadIdx.x;

    // ---- stage fused weights ----
    for (int i = tid; i < 2800; i += NTHR) {
        int g = i / 28, p = i - g * 28;
        float v = 0.f;
        if (p == 0)      v = Wih1[g];
        else if (p < 26) v = Whh1[g * 25 + p - 1];
        smem[W0_OFF + i] = v;
    }
    {
        const float* WihL[3] = {Wih2, Wih3, Wih4};
        const float* WhhL[3] = {Whh2, Whh3, Whh4};
        for (int i = tid; i < 15600; i += NTHR) {
            int l = i / 5200; int r = i - l * 5200;
            int g = r / 52,   p = r - g * 52;
            float v = 0.f;
            if (p < 25)                 v = WihL[l][g * 25 + p];
            else if (p >= 26 && p < 51) v = WhhL[l][g * 25 + p - 26];
            smem[W123_OFF + i] = v;
        }
        const float* bi[4] = {bih1, bih2, bih3, bih4};
        const float* bh[4] = {bhh1, bhh2, bhh3, bhh4};
        for (int i = tid; i < 400; i += NTHR) {
            int l = i / 100, g = i - l * 100;
            smem[BIAS_OFF + i] = bi[l][g] + bh[l][g];
        }
    }
    for (int i = tid; i < 52; i += NTHR)
        smem[WFC_OFF + i] = (i >= 26 && i < 51) ? Wfc[i - 26] : 0.f;
    for (int i = tid; i < 1792 + 9984; i += NTHR) smem[V0_OFF + i] = 0.f;
    __syncthreads();

    const int lane = tid & 31;
    const int u    = tid >> 5;                  // hidden unit 0..24
    const int gb   = (blockIdx.x << 5) + lane;  // global batch element

    float xreg = 0.f, bfc_reg = 0.f;
    if (u == 0) {
        smem[V0_OFF + lane * 28 + 0] = x[gb];   // x_0 -> buffer 0
        xreg = x[(size_t)NB + gb];              // prefetch x_1
    }
    if (u == 1) bfc_reg = bfc[0];
    __syncthreads();

    float c0 = 0.f, c1 = 0.f, c2 = 0.f, c3 = 0.f;
    float h0r = 0.f, h1r = 0.f, h2r = 0.f, h3r = 0.f;

    float* v0b = smem + V0_OFF   + lane * 28;
    float* v1b = smem + V123_OFF + lane * 52;
    float* v2b = v1b + 3328;
    float* v3b = v2b + 3328;
    const float* w0  = smem + W0_OFF   + u * 28;   // gate j row: +j*700
    const float* wl1 = smem + W123_OFF + u * 52;   // gate j row: +j*1300
    const float* wl2 = wl1 + 5200;
    const float* wl3 = wl2 + 5200;
    const float* bias = smem + BIAS_OFF;
    const float* wfc  = smem + WFC_OFF;

    for (int t = 0; t < Tlen; ++t) {
        const int cur = t & 1, nxt = cur ^ 1;
        float* v0c = v0b + cur * 896;  float* v0n = v0b + nxt * 896;
        float* v1c = v1b + cur * 1664; float* v1n = v1b + nxt * 1664;
        float* v2c = v2b + cur * 1664; float* v2n = v2b + nxt * 1664;
        float* v3c = v3b + cur * 1664; float* v3n = v3b + nxt * 1664;

        if (u == 0) {                       // stage x_{t+1}; prefetch x_{t+2}
            v0n[0] = xreg;
            int t2 = (t + 2 < Tlen) ? t + 2 : Tlen - 1;
            xreg = x[(size_t)t2 * NB + gb];
        }
        if (u == 1 && t > 0) {              // fc head, one step behind
            out[(size_t)(t - 1) * NB + gb] = fc_dot(v3c, wfc) + bfc_reg;
        }

        {   // layer 1: v = [x_t, h1(t-1)], 28 floats
            float s0, s1, s2, s3;
            gates4<7>(v0c, w0, w0 + 700, w0 + 1400, w0 + 2100,
                      bias[u], bias[25 + u], bias[50 + u], bias[75 + u],
                      s0, s1, s2, s3);
            float h = lstm_update(s0, s1, s2, s3, c0);
            h0r = h; v0n[1 + u] = h; v1c[u] = h;   // self->next buf, feed L2 this step
        }
        __syncthreads();
        {   // layer 2: v1c = [h1(t), pad, h2(t-1), pad]
            float s0, s1, s2, s3;
            gates4<13>(v1c, wl1, wl1 + 1300, wl1 + 2600, wl1 + 3900,
                       bias[100 + u], bias[125 + u], bias[150 + u], bias[175 + u],
                       s0, s1, s2, s3);
            float h = lstm_update(s0, s1, s2, s3, c1);
            h1r = h; v1n[26 + u] = h; v2c[u] = h;
        }
        __syncthreads();
        {   // layer 3
            float s0, s1, s2, s3;
            gates4<13>(v2c, wl2, wl2 + 1300, wl2 + 2600, wl2 + 3900,
                       bias[200 + u], bias[225 + u], bias[250 + u], bias[275 + u],
                       s0, s1, s2, s3);
            float h = lstm_update(s0, s1, s2, s3, c2);
            h2r = h; v2n[26 + u] = h; v3c[u] = h;
        }
        __syncthreads();
        {   // layer 4
            float s0, s1, s2, s3;
            gates4<13>(v3c, wl3, wl3 + 1300, wl3 + 2600, wl3 + 3900,
                       bias[300 + u], bias[325 + u], bias[350 + u], bias[375 + u],
                       s0, s1, s2, s3);
            float h = lstm_update(s0, s1, s2, s3, c3);
            h3r = h; v3n[26 + u] = h;
        }
        __syncthreads();
    }

    // final fc: h4(T-1) sits in v3 buffer (Tlen & 1) = 0
    if (u == 1) {
        out[(size_t)(Tlen - 1) * NB + gb] = fc_dot(v3b + (Tlen & 1) * 1664, wfc) + bfc_reg;
    }

    // final states (h1,c1,h2,c2,h3,c3,h4,c4), each [4096,25], after y
    if (write_states) {
        size_t base = (size_t)Tlen * NB;
        size_t idx  = (size_t)gb * 25 + u;
        const size_t S = (size_t)NB * 25;
        out[base + 0 * S + idx] = h0r;
        out[base + 1 * S + idx] = c0;
        out[base + 2 * S + idx] = h1r;
        out[base + 3 * S + idx] = c1;
        out[base + 4 * S + idx] = h2r;
        out[base + 5 * S + idx] = c2;
        out[base + 6 * S + idx] = h3r;
        out[base + 7 * S + idx] = c3;
    }
}

extern "C" void kernel_launch(void* const* d_in, const int* in_sizes, int n_in,
                              void* d_out, int out_size) {
    (void)n_in;
    const float* x    = (const float*)d_in[0];
    const float* Wih1 = (const float*)d_in[1];
    const float* Whh1 = (const float*)d_in[2];
    const float* bih1 = (const float*)d_in[3];
    const float* bhh1 = (const float*)d_in[4];
    const float* Wih2 = (const float*)d_in[5];
    const float* Whh2 = (const float*)d_in[6];
    const float* bih2 = (const float*)d_in[7];
    const float* bhh2 = (const float*)d_in[8];
    const float* Wih3 = (const float*)d_in[9];
    const float* Whh3 = (const float*)d_in[10];
    const float* bih3 = (const float*)d_in[11];
    const float* bhh3 = (const float*)d_in[12];
    const float* Wih4 = (const float*)d_in[13];
    const float* Whh4 = (const float*)d_in[14];
    const float* bih4 = (const float*)d_in[15];
    const float* bhh4 = (const float*)d_in[16];
    const float* Wfc  = (const float*)d_in[17];
    const float* bfc  = (const float*)d_in[18];
    (void)in_sizes;

    int smem_bytes = SMEM_FLOATS * (int)sizeof(float);
    static int configured = -1;
    if (configured != smem_bytes) {
        cudaFuncSetAttribute(lstm_kernel,
                             cudaFuncAttributeMaxDynamicSharedMemorySize, smem_bytes);
        configured = smem_bytes;
    }
    // y is 512*4096 = 2097152 floats; with final states it's 2916352.
    int write_states = (out_size >= Tlen * NB + 8 * NB * 25) ? 1 : 0;

    lstm_kernel<<<NB / 32, NTHR, smem_bytes>>>(
        x, Wih1, Whh1, bih1, bhh1,
        Wih2, Whh2, bih2, bhh2,
        Wih3, Whh3, bih3, bhh3,
        Wih4, Whh4, bih4, bhh4,
        Wfc, bfc, (float*)d_out, write_states);
}